// round 15
// baseline (speedup 1.0000x reference)
#include <cuda_runtime.h>
#include <math.h>
#include <stdint.h>

#define SEQ 2048
#define HID 2048
#define NH  16
#define NKV 8
#define HD  128

typedef unsigned long long ull;

// Scratch (allocation-free: __device__ globals).
// RULE: only touched from host code in kernel_launch (decayed pointers passed
// as kernel args). Mixing device-symbol and host-decayed addressing caused the
// R10/R12 correctness failures.
__device__ float g_q[(size_t)SEQ * NH * HD];
__device__ float g_k[(size_t)SEQ * NKV * HD];
__device__ float g_v[(size_t)SEQ * NKV * HD];
__device__ float g_ctx[(size_t)SEQ * NH * HD];

// ---------------------------------------------------------------------------
// packed f32x2 helpers
// ---------------------------------------------------------------------------
__device__ __forceinline__ void ffma2(ull& acc, ull a, ull b) {
    asm("fma.rn.f32x2 %0, %1, %2, %0;" : "+l"(acc) : "l"(a), "l"(b));
}
__device__ __forceinline__ ull dup2(float v) {
    ull r;
    asm("mov.b64 %0, {%1, %1};" : "=l"(r) : "f"(v));
    return r;
}
__device__ __forceinline__ float2 unpack2(ull v) {
    float2 f;
    asm("mov.b64 {%0, %1}, %2;" : "=f"(f.x), "=f"(f.y) : "l"(v));
    return f;
}
__device__ __forceinline__ void cpasync16(uint32_t s, const void* g) {
    asm volatile("cp.async.cg.shared.global [%0], [%1], 16;\n" :: "r"(s), "l"(g));
}
#define CPASYNC_COMMIT() asm volatile("cp.async.commit_group;\n" ::: "memory")
#define CPASYNC_WAIT0()  asm volatile("cp.async.wait_group 0;\n" ::: "memory")
#define CPASYNC_WAIT1()  asm volatile("cp.async.wait_group 1;\n" ::: "memory")

// ---------------------------------------------------------------------------
// GEMM core v2 (proven R14): 128x128 CTA tile, 512 threads, BK=32.
// ---------------------------------------------------------------------------
#define BKG 32
#define ADUP_W 256
#define BS_W   132
#define STAGE_F (BKG * ADUP_W + BKG * BS_W)
#define GEMM_SMEM (2 * STAGE_F * 4)

__device__ __forceinline__
void gemm_core(const float* __restrict__ A, const float* __restrict__ Btile,
               float* __restrict__ Ctile, int lda, int ldb, int ldc,
               int m0, int K, float* smf)
{
    const int tid  = threadIdx.x;
    const int tx   = tid & 31;
    const int ty   = tid >> 5;
    const int grow = tid >> 2;
    const int gc8  = (tid & 3) * 8;

    ull acc[8][2];
    #pragma unroll
    for (int i = 0; i < 8; i++) { acc[i][0] = 0ull; acc[i][1] = 0ull; }

    float4 aR0, aR1, bR0, bR1;

    auto ldg_stage = [&](int k0) {
        const float* ap = A + (long long)(m0 + grow) * lda + k0 + gc8;
        aR0 = *(const float4*)ap;
        aR1 = *(const float4*)(ap + 4);
        const float* bp = Btile + (long long)grow * ldb + k0 + gc8;
        bR0 = *(const float4*)bp;
        bR1 = *(const float4*)(bp + 4);
    };
    auto sts_stage = [&](int buf) {
        ull*   sAd = (ull*)(smf + buf * STAGE_F);
        float* sB  = smf + buf * STAGE_F + BKG * ADUP_W;
        sAd[(gc8 + 0) * 128 + grow] = dup2(aR0.x);
        sAd[(gc8 + 1) * 128 + grow] = dup2(aR0.y);
        sAd[(gc8 + 2) * 128 + grow] = dup2(aR0.z);
        sAd[(gc8 + 3) * 128 + grow] = dup2(aR0.w);
        sAd[(gc8 + 4) * 128 + grow] = dup2(aR1.x);
        sAd[(gc8 + 5) * 128 + grow] = dup2(aR1.y);
        sAd[(gc8 + 6) * 128 + grow] = dup2(aR1.z);
        sAd[(gc8 + 7) * 128 + grow] = dup2(aR1.w);
        sB[(gc8 + 0) * BS_W + grow] = bR0.x;
        sB[(gc8 + 1) * BS_W + grow] = bR0.y;
        sB[(gc8 + 2) * BS_W + grow] = bR0.z;
        sB[(gc8 + 3) * BS_W + grow] = bR0.w;
        sB[(gc8 + 4) * BS_W + grow] = bR1.x;
        sB[(gc8 + 5) * BS_W + grow] = bR1.y;
        sB[(gc8 + 6) * BS_W + grow] = bR1.z;
        sB[(gc8 + 7) * BS_W + grow] = bR1.w;
    };

    ldg_stage(0);
    sts_stage(0);
    __syncthreads();

    const int nIter = K / BKG;
    int buf = 0;
    for (int it = 0; it < nIter; it++) {
        const bool hasNext = (it + 1) < nIter;
        if (hasNext) ldg_stage((it + 1) * BKG);

        const ull*   Ad = (const ull*)(smf + buf * STAGE_F);
        const float* Bf = smf + buf * STAGE_F + BKG * ADUP_W;

        #pragma unroll
        for (int kk = 0; kk < BKG; kk++) {
            const ull* arow = Ad + kk * 128 + ty * 8;
            const ulonglong2 a01 = *(const ulonglong2*)(arow + 0);
            const ulonglong2 a23 = *(const ulonglong2*)(arow + 2);
            const ulonglong2 a45 = *(const ulonglong2*)(arow + 4);
            const ulonglong2 a67 = *(const ulonglong2*)(arow + 6);
            const ulonglong2 b   = *(const ulonglong2*)((const ull*)(Bf + kk * BS_W) + tx * 2);
            ffma2(acc[0][0], a01.x, b.x); ffma2(acc[0][1], a01.x, b.y);
            ffma2(acc[1][0], a01.y, b.x); ffma2(acc[1][1], a01.y, b.y);
            ffma2(acc[2][0], a23.x, b.x); ffma2(acc[2][1], a23.x, b.y);
            ffma2(acc[3][0], a23.y, b.x); ffma2(acc[3][1], a23.y, b.y);
            ffma2(acc[4][0], a45.x, b.x); ffma2(acc[4][1], a45.x, b.y);
            ffma2(acc[5][0], a45.y, b.x); ffma2(acc[5][1], a45.y, b.y);
            ffma2(acc[6][0], a67.x, b.x); ffma2(acc[6][1], a67.x, b.y);
            ffma2(acc[7][0], a67.y, b.x); ffma2(acc[7][1], a67.y, b.y);
        }

        if (hasNext) sts_stage(buf ^ 1);
        __syncthreads();
        buf ^= 1;
    }

    #pragma unroll
    for (int i = 0; i < 8; i++) {
        const float2 p0 = unpack2(acc[i][0]);
        const float2 p1 = unpack2(acc[i][1]);
        *(float4*)(Ctile + (long long)(m0 + ty * 8 + i) * ldc + tx * 4) =
            make_float4(p0.x, p0.y, p1.x, p1.y);
    }
}

__global__ __launch_bounds__(512, 1)
void gemm_qkv(const float* __restrict__ x,
              const float* __restrict__ Wq, const float* __restrict__ Wk,
              const float* __restrict__ Wv,
              float* __restrict__ qo, float* __restrict__ ko,
              float* __restrict__ vo)
{
    extern __shared__ float smf[];
    const int bx = blockIdx.x;
    const float* B;
    float* out;
    int ldc, nc0;
    if (bx < 16)      { B = Wq + (size_t)bx * 128 * 2048;        out = qo; ldc = 2048; nc0 = bx * 128; }
    else if (bx < 24) { B = Wk + (size_t)(bx - 16) * 128 * 2048; out = ko; ldc = 1024; nc0 = (bx - 16) * 128; }
    else              { B = Wv + (size_t)(bx - 24) * 128 * 2048; out = vo; ldc = 1024; nc0 = (bx - 24) * 128; }

    gemm_core(x, B, out + nc0, 2048, 2048, ldc, blockIdx.y * 128, 2048, smf);
}

__global__ __launch_bounds__(512, 1)
void gemm_nt(const float* __restrict__ A, const float* __restrict__ B,
             float* __restrict__ C)
{
    extern __shared__ float smf[];
    const int n0 = blockIdx.x * 128;
    gemm_core(A, B + (size_t)n0 * 2048, C + n0, 2048, 2048, 2048,
              blockIdx.y * 128, 2048, smf);
}

// ---------------------------------------------------------------------------
// Combined RoPE for Q (16 heads) and K (8 heads), in-place. One launch.
// ---------------------------------------------------------------------------
#define QROPE_N (SEQ * NH * (HD / 2))
#define KROPE_N (SEQ * NKV * (HD / 2))

__global__ void rope_both_kernel(float* __restrict__ q, float* __restrict__ k,
                                 const float* __restrict__ cosT,
                                 const float* __restrict__ sinT)
{
    int idx = blockIdx.x * blockDim.x + threadIdx.x;
    float* t;
    int heads;
    if (idx < QROPE_N) { t = q; heads = NH; }
    else {
        idx -= QROPE_N;
        if (idx >= KROPE_N) return;
        t = k; heads = NKV;
    }
    const int d = idx % (HD / 2);
    const int h = (idx / (HD / 2)) % heads;
    const int s = idx / ((HD / 2) * heads);

    const float c1 = cosT[s * HD + d];
    const float s1 = sinT[s * HD + d];
    const float c2 = cosT[s * HD + d + HD / 2];
    const float s2 = sinT[s * HD + d + HD / 2];

    float* row = t + (long long)s * heads * HD + h * HD;
    const float x1 = row[d];
    const float x2 = row[d + HD / 2];
    row[d]          = x1 * c1 - x2 * s1;
    row[d + HD / 2] = x2 * c2 + x1 * s2;
}

// ---------------------------------------------------------------------------
// Flash attention v2: dup-free inner loops.
//  - Q kept in NATURAL [q][d] layout; S-GEMM accumulates packed (even-d,odd-d)
//    partial sums via FFMA2 on contiguous d-pairs of Q and K rows, then one
//    horizontal add per S element. No dup2 in the d-loop.
//  - softmax writes P as (p,p) dup'd ull pairs into sSd; PV reads P via plain
//    LDS.64. No dup2 in the kk-loop.
// Thread maps: S-GEMM tq=tid&15 (q rows tq+16j), tk=tid>>4 (k cols tk*4..+3).
// PV: tyO=tid>>4 (q rows tyO*4..+3), txO=tid&15 (d cols txO*8..+7).
// ---------------------------------------------------------------------------
#define BQ 64
#define BKT 64
#define KVSTR 132
#define QSTR  132
#define SDSTR 66                 // ull stride of dup'd S rows (=132 floats)
#define OFF_Q  0                                   // 64*132       = 8448 f
#define OFF_K  (OFF_Q + BQ * QSTR)                 // +2*64*132    = 16896 f
#define OFF_V  (OFF_K + 2 * BKT * KVSTR)
#define OFF_SD (OFF_V + 2 * BKT * KVSTR)           // 64*66 ull    = 8448 f
#define OFF_M  (OFF_SD + BQ * SDSTR * 2)
#define OFF_L  (OFF_M + 64)
#define OFF_AL (OFF_L + 64)
#define FA_SMEM ((OFF_AL + 64) * 4)                // ~203.6 KB

__global__ __launch_bounds__(256, 1)
void flash_kernel(const float* __restrict__ q, const float* __restrict__ k,
                  const float* __restrict__ v, float* __restrict__ ctx)
{
    extern __shared__ float fs[];
    float* sQ  = fs + OFF_Q;
    ull*   sSd = (ull*)(fs + OFF_SD);
    float* sM  = fs + OFF_M;
    float* sL  = fs + OFF_L;
    float* sAl = fs + OFF_AL;

    const int qt = (int)gridDim.x - 1 - (int)blockIdx.x;   // long CTAs first
    const int h  = blockIdx.y;
    const int q0 = qt * BQ;
    const int tid = threadIdx.x;
    const int nt = qt + 1;
    const float qscale = 0.08838834764831845f;   // 1/sqrt(128)

    const uint32_t sbase = (uint32_t)__cvta_generic_to_shared(fs);

    // load Q tile (scaled) in NATURAL layout sQ[q][d]
    {
        const int r = tid >> 2, seg = tid & 3;
        const float* gp = q + (size_t)(q0 + r) * (NH * HD) + h * HD + seg * 32;
        float* sp = sQ + r * QSTR + seg * 32;
        #pragma unroll
        for (int i = 0; i < 8; i++) {
            float4 f4 = ((const float4*)gp)[i];
            f4.x *= qscale; f4.y *= qscale; f4.z *= qscale; f4.w *= qscale;
            *(float4*)(sp + i * 4) = f4;
        }
    }
    if (tid < 64) { sM[tid] = -INFINITY; sL[tid] = 0.0f; }

    const int lr = tid >> 2, lseg = tid & 3;
    const float* kbase = k + (size_t)lr * (NKV * HD) + (h >> 1) * HD + lseg * 32;
    const float* vbase = v + (size_t)lr * (NKV * HD) + (h >> 1) * HD + lseg * 32;
    auto loadKV = [&](int buf, int t) {
        const size_t goff = (size_t)t * BKT * (NKV * HD);
        const uint32_t sk = sbase + (uint32_t)(OFF_K + buf * BKT * KVSTR + lr * KVSTR + lseg * 32) * 4;
        const uint32_t sv = sbase + (uint32_t)(OFF_V + buf * BKT * KVSTR + lr * KVSTR + lseg * 32) * 4;
        const float* kp = kbase + goff;
        const float* vp = vbase + goff;
        #pragma unroll
        for (int i = 0; i < 8; i++) {
            cpasync16(sk + i * 16, kp + i * 4);
            cpasync16(sv + i * 16, vp + i * 4);
        }
        CPASYNC_COMMIT();
    };

    const int tq = tid & 15;       // S: q rows tq + 16j
    const int tk = tid >> 4;       // S: k cols tk*4..+3
    const int tyO = tid >> 4;      // PV: q rows tyO*4..+3
    const int txO = tid & 15;      // PV: d cols txO*8..+7
    const int sr = tid >> 2, ssub = tid & 3;   // softmax: row, 16-k segment

    ull accO[4][4];
    #pragma unroll
    for (int i = 0; i < 4; i++)
        #pragma unroll
        for (int j = 0; j < 4; j++) accO[i][j] = 0ull;

    loadKV(0, 0);

    for (int t = 0; t < nt; t++) {
        const int buf = t & 1;
        if (t + 1 < nt) { loadKV(buf ^ 1, t + 1); CPASYNC_WAIT1(); }
        else            { CPASYNC_WAIT0(); }
        __syncthreads();   // tile ready; prior PV done with sSd

        // ---- S = Q·K^T  (packed d-pairs; no dup2) ----
        {
            const float* sK = fs + OFF_K + buf * BKT * KVSTR;
            ull accS[4][4];
            #pragma unroll
            for (int a = 0; a < 4; a++)
                #pragma unroll
                for (int b = 0; b < 4; b++) accS[a][b] = 0ull;

            #pragma unroll 4
            for (int dc = 0; dc < HD; dc += 4) {
                ulonglong2 qf[4];
                #pragma unroll
                for (int i = 0; i < 4; i++)
                    qf[i] = *(const ulonglong2*)(sQ + (tq + 16 * i) * QSTR + dc);
                #pragma unroll
                for (int j = 0; j < 4; j++) {
                    const ulonglong2 kf =
                        *(const ulonglong2*)(sK + (tk * 4 + j) * KVSTR + dc);
                    #pragma unroll
                    for (int i = 0; i < 4; i++) {
                        ffma2(accS[i][j], qf[i].x, kf.x);
                        ffma2(accS[i][j], qf[i].y, kf.y);
                    }
                }
            }
            // horizontal add + dup'd store to sSd
            #pragma unroll
            for (int i = 0; i < 4; i++) {
                ull* srow = sSd + (tq + 16 * i) * SDSTR + tk * 4;
                #pragma unroll
                for (int j = 0; j < 4; j++) {
                    const float2 f = unpack2(accS[i][j]);
                    srow[j] = dup2(f.x + f.y);
                }
            }
        }
        __syncthreads();

        // ---- online softmax (reads/writes dup'd S) ----
        {
            float vals[16];
            float4* srow4 = (float4*)(sSd + sr * SDSTR + ssub * 16);
            #pragma unroll
            for (int i = 0; i < 8; i++) {
                const float4 f4 = srow4[i];   // (p,p,p',p')
                vals[2 * i]     = f4.x;
                vals[2 * i + 1] = f4.z;
            }
            if (t == nt - 1) {   // diagonal tile: mask k > q
                #pragma unroll
                for (int i = 0; i < 16; i++)
                    if (ssub * 16 + i > sr) vals[i] = -INFINITY;
            }
            float vmax = vals[0];
            #pragma unroll
            for (int i = 1; i < 16; i++) vmax = fmaxf(vmax, vals[i]);
            vmax = fmaxf(vmax, __shfl_xor_sync(0xFFFFFFFFu, vmax, 1));
            vmax = fmaxf(vmax, __shfl_xor_sync(0xFFFFFFFFu, vmax, 2));
            const float mprev = sM[sr];
            const float mnew  = fmaxf(mprev, vmax);
            float ssum = 0.0f;
            #pragma unroll
            for (int i = 0; i < 16; i++) {
                const float p = __expf(vals[i] - mnew);
                vals[i] = p;
                ssum += p;
            }
            ssum += __shfl_xor_sync(0xFFFFFFFFu, ssum, 1);
            ssum += __shfl_xor_sync(0xFFFFFFFFu, ssum, 2);
            #pragma unroll
            for (int i = 0; i < 8; i++)
                srow4[i] = make_float4(vals[2 * i], vals[2 * i],
                                       vals[2 * i + 1], vals[2 * i + 1]);
            if (ssub == 0) {
                const float alpha = __expf(mprev - mnew);
                sL[sr] = sL[sr] * alpha + ssum;
                sM[sr] = mnew;
                sAl[sr] = alpha;
            }
        }
        __syncthreads();

        // ---- O = O*alpha + P·V  (P read as pre-dup'd ull; no dup2) ----
        {
            const float* sV = fs + OFF_V + buf * BKT * KVSTR;
            #pragma unroll
            for (int i = 0; i < 4; i++) {
                const float al = sAl[tyO * 4 + i];
                #pragma unroll
                for (int j = 0; j < 4; j++) {
                    float2 f = unpack2(accO[i][j]);
                    f.x *= al; f.y *= al;
                    ull packed;
                    asm("mov.b64 %0, {%1, %2};" : "=l"(packed) : "f"(f.x), "f"(f.y));
                    accO[i][j] = packed;
                }
            }
            #pragma unroll 2
            for (int kk = 0; kk < BKT; kk++) {
                const ull* vrow = (const ull*)(sV + kk * KVSTR + txO * 8);
                const ull v0 = vrow[0], v1 = vrow[1], v2 = vrow[2], v3 = vrow[3];
                #pragma unroll
                for (int i = 0; i < 4; i++) {
                    const ull pd = sSd[(tyO * 4 + i) * SDSTR + kk];
                    ffma2(accO[i][0], pd, v0);
                    ffma2(accO[i][1], pd, v1);
                    ffma2(accO[i][2], pd, v2);
                    ffma2(accO[i][3], pd, v3);
                }
            }
        }
        __syncthreads();   // protect sV/sSd before next tile's loads/writes
    }

    // ---- normalize and write O ----
    #pragma unroll
    for (int i = 0; i < 4; i++) {
        const int r = tyO * 4 + i;
        const float inv = 1.0f / sL[r];
        float o[8];
        #pragma unroll
        for (int j = 0; j < 4; j++) {
            const float2 f = unpack2(accO[i][j]);
            o[2 * j]     = f.x * inv;
            o[2 * j + 1] = f.y * inv;
        }
        float* cp = ctx + (size_t)(q0 + r) * (NH * HD) + h * HD + txO * 8;
        *(float4*)cp       = make_float4(o[0], o[1], o[2], o[3]);
        *(float4*)(cp + 4) = make_float4(o[4], o[5], o[6], o[7]);
    }
}

// ---------------------------------------------------------------------------
extern "C" void kernel_launch(void* const* d_in, const int* in_sizes, int n_in,
                              void* d_out, int out_size)
{
    const float* x    = (const float*)d_in[0];
    const float* Wq   = (const float*)d_in[1];
    const float* Wk   = (const float*)d_in[2];
    const float* Wv   = (const float*)d_in[3];
    const float* Wo   = (const float*)d_in[4];
    const float* cosT = (const float*)d_in[5];
    const float* sinT = (const float*)d_in[6];
    float* out = (float*)d_out;

    // host-decayed scratch pointers — the ONLY place g_* symbols are touched
    float* q   = g_q;
    float* k   = g_k;
    float* v   = g_v;
    float* ctx = g_ctx;

    cudaFuncSetAttribute(gemm_qkv,     cudaFuncAttributeMaxDynamicSharedMemorySize, GEMM_SMEM);
    cudaFuncSetAttribute(gemm_nt,      cudaFuncAttributeMaxDynamicSharedMemorySize, GEMM_SMEM);
    cudaFuncSetAttribute(flash_kernel, cudaFuncAttributeMaxDynamicSharedMemorySize, FA_SMEM);

    // 1) fused QKV projections (512 CTAs x 512 threads)
    gemm_qkv<<<dim3(32, 16), dim3(512), GEMM_SMEM>>>(x, Wq, Wk, Wv, q, k, v);

    // 2) RoPE on Q and K in one launch
    {
        const int total = QROPE_N + KROPE_N;
        rope_both_kernel<<<(total + 255) / 256, dim3(256)>>>(q, k, cosT, sinT);
    }

    // 3) flash attention (causal, GQA 2:1, dup-free inner loops)
    flash_kernel<<<dim3(SEQ / BQ, NH), dim3(256), FA_SMEM>>>(q, k, v, ctx);

    // 4) out = ctx @ Wo^T
    gemm_nt<<<dim3(16, 16), dim3(512), GEMM_SMEM>>>(ctx, Wo, out);
}